// round 3
// baseline (speedup 1.0000x reference)
#include <cuda_runtime.h>
#include <math.h>

#define Hh 1024
#define Ww 1024
#define Cc 16
#define HW (1024*1024)

#define ZD (-0.26794919243112270647)   // sqrt(3) - 2

static __device__ float  g_coef[Cc*HW];   // fully prefiltered image coefficients
static __device__ float  g_dcoef[18];     // prefiltered control-point displacements (2x3x3)
static __device__ float4 g_wy4[1024];     // strict cubic weights per coordinate
static __device__ int    g_myp[1024];     // packed mirrored indices (2 bits x 4)
static __device__ float  g_R[6*1024];     // folded x-direction displacement rows [ch*3+j][x]

// --- exact reference 3-point spline_filter1d (horizon = 3), eager-mode fp32 --
__device__ __forceinline__ void filt3(float v0, float v1, float v2, float* o) {
    const float Zf    = (float)ZD;
    const float Z2f   = (float)(ZD*ZD);
    const float GAIN  = 6.0f;                      // (1-z)(1-1/z) = 6 exactly
    const float LASTC = (float)(ZD/(ZD*ZD-1.0));
    float c0 = __fmul_rn(v0, GAIN);
    float c1 = __fmul_rn(v1, GAIN);
    float c2 = __fmul_rn(v2, GAIN);
    float cp0 = c0;
    cp0 = __fmaf_rn(Zf,  c1, cp0);
    cp0 = __fmaf_rn(Z2f, c2, cp0);
    float cp1 = __fadd_rn(c1, __fmul_rn(Zf, cp0));
    float cp2 = __fadd_rn(c2, __fmul_rn(Zf, cp1));
    float last = __fmul_rn(LASTC, __fadd_rn(cp2, __fmul_rn(Zf, cp1)));
    float o1 = __fmul_rn(Zf, __fsub_rn(last, cp1));
    float o0 = __fmul_rn(Zf, __fsub_rn(o1,  cp0));
    o[0] = o0; o[1] = o1; o[2] = last;
}

__global__ void setup_kernel(const float* __restrict__ disp) {
    if (threadIdx.x == 0) {
        float d[2][3][3];
        for (int ch = 0; ch < 2; ch++)
            for (int i = 0; i < 3; i++)
                for (int j = 0; j < 3; j++)
                    d[ch][i][j] = __fmul_rn(disp[ch*9 + i*3 + j], 10.0f);   // SIGMA
        for (int ch = 0; ch < 2; ch++)
            for (int j = 0; j < 3; j++) {
                float o[3];
                filt3(d[ch][0][j], d[ch][1][j], d[ch][2][j], o);
                d[ch][0][j] = o[0]; d[ch][1][j] = o[1]; d[ch][2][j] = o[2];
            }
        for (int ch = 0; ch < 2; ch++)
            for (int i = 0; i < 3; i++) {
                float o[3];
                filt3(d[ch][i][0], d[ch][i][1], d[ch][i][2], o);
                g_dcoef[ch*9 + i*3 + 0] = o[0];
                g_dcoef[ch*9 + i*3 + 1] = o[1];
                g_dcoef[ch*9 + i*3 + 2] = o[2];
            }
    }
}

// --- strict (eager-jax) cubic weights: exact primitive-by-primitive ----------
__device__ __forceinline__ void cubw_strict(float f, float* w) {
    float f2 = __fmul_rn(f, f);
    float f3 = __fmul_rn(f2, f);
    float t = __fsub_rn(1.0f, __fmul_rn(3.0f, f));
    t = __fadd_rn(t, __fmul_rn(3.0f, f2));
    t = __fsub_rn(t, f3);
    w[0] = __fdiv_rn(t, 6.0f);
    t = __fsub_rn(4.0f, __fmul_rn(6.0f, f2));
    t = __fadd_rn(t, __fmul_rn(3.0f, f3));
    w[1] = __fdiv_rn(t, 6.0f);
    t = __fadd_rn(1.0f, __fmul_rn(3.0f, f));
    t = __fadd_rn(t, __fmul_rn(3.0f, f2));
    t = __fsub_rn(t, __fmul_rn(3.0f, f3));
    w[2] = __fdiv_rn(t, 6.0f);
    w[3] = __fdiv_rn(f3, 6.0f);
}

__device__ __forceinline__ int mir3(int i) {        // mirror, n=3 (period 4)
    int m = i < 0 ? -i : i;
    m &= 3;
    return m > 2 ? 4 - m : m;
}
__device__ __forceinline__ int refl1024(int i) {    // mirror, n=1024 (small excursions)
    return i < 0 ? -i : (i > 1023 ? 2046 - i : i);
}

// --- per-coordinate strict weight tables + folded displacement rows ----------
__global__ void table_kernel() {
    int i = blockIdx.x * 256 + threadIdx.x;         // coordinate 0..1023
    const float SCL = (float)(2.0/1023.0);
    float u = __fmul_rn((float)i, SCL);
    float fl = floorf(u); int i0 = (int)fl;
    float f = __fsub_rn(u, fl);
    float w[4];
    cubw_strict(f, w);
    int m[4];
    #pragma unroll
    for (int b = 0; b < 4; b++) m[b] = mir3(i0 + b - 1);
    g_wy4[i] = make_float4(w[0], w[1], w[2], w[3]);
    g_myp[i] = m[0] | (m[1] << 2) | (m[2] << 4) | (m[3] << 6);
    // fold x-weights into displacement rows with EXACT reference op order:
    // row(j, x) = (((0 + w0*D[j][m0]) + w1*D[j][m1]) + w2*D[j][m2]) + w3*D[j][m3]
    #pragma unroll
    for (int ch = 0; ch < 2; ch++)
        #pragma unroll
        for (int j = 0; j < 3; j++) {
            float r = 0.0f;
            #pragma unroll
            for (int b = 0; b < 4; b++)
                r = __fadd_rn(r, __fmul_rn(w[b], g_dcoef[ch*9 + j*3 + m[b]]));
            g_R[(ch*3 + j)*1024 + i] = r;
        }
}

// --- fused row+col cubic B-spline prefilter (in-place IIR in smem) ----------
// Out tile 128x128, 16-sample halo on all sides, mirror-indexed loads.
// Truncation error ~ z^16 (~7e-10): far below image tolerance.
#define TP 161                     // smem pitch (161 % 32 == 1 -> conflict-free)
#define PSMEM (160*TP*4)
__global__ void __launch_bounds__(256) prefilt_kernel(const float* __restrict__ img) {
    extern __shared__ float S[];   // [160][161]
    int x0 = blockIdx.x * 128 - 16;
    int y0 = blockIdx.y * 128 - 16;
    int ch = blockIdx.z;
    const float* base = img + ch * HW;
    const float Zf = (float)ZD;

    // Stage A: load (mirror-indexed) tile, pre-multiplied by gain=6
    for (int idx = threadIdx.x; idx < 160*160; idx += 256) {
        int r = idx / 160, c = idx - r*160;
        int gy = refl1024(y0 + r);
        int gx = refl1024(x0 + c);
        S[r*TP + c] = 6.0f * __ldg(base + gy*Ww + gx);
    }
    __syncthreads();

    // Stage B: row IIR (causal then anticausal), in place
    if (threadIdx.x < 160) {
        float* p = S + threadIdx.x * TP;
        float A = p[0];
        #pragma unroll 8
        for (int c = 1; c < 160; c++) { A = fmaf(Zf, A, p[c]); p[c] = A; }
        float Rv = 0.0f;
        #pragma unroll 8
        for (int c = 159; c >= 0; c--) { Rv = Zf * (Rv - p[c]); p[c] = Rv; }
    }
    __syncthreads();

    // Stage C: column IIR on the 128 output columns (gain 6 applied on read)
    if (threadIdx.x < 128) {
        float* p = S + 16 + threadIdx.x;
        float A = 6.0f * p[0];
        p[0] = A;
        #pragma unroll 8
        for (int r = 1; r < 160; r++) { A = fmaf(Zf, A, 6.0f * p[r*TP]); p[r*TP] = A; }
        float Rv = 0.0f;
        #pragma unroll 8
        for (int r = 159; r >= 0; r--) { Rv = Zf * (Rv - p[r*TP]); p[r*TP] = Rv; }
    }
    __syncthreads();

    // Stage D: write 128x128 output tile
    float* ob = g_coef + ch*HW + (blockIdx.y*128)*Ww + blockIdx.x*128;
    for (int idx = threadIdx.x; idx < 128*128; idx += 256) {
        int r = idx >> 7, c = idx & 127;
        ob[r*Ww + c] = S[(16 + r)*TP + 16 + c];
    }
}

// fast weights for the image gather (loose tolerance path)
__device__ __forceinline__ void cubw_fast(float f, float* w) {
    float f2 = f*f;
    float f3 = f2*f;
    const float S = 1.0f/6.0f;
    w[0] = (1.0f - 3.0f*f + 3.0f*f2 - f3) * S;
    w[1] = (4.0f - 6.0f*f2 + 3.0f*f3) * S;
    w[2] = (1.0f + 3.0f*f + 3.0f*f2 - 3.0f*f3) * S;
    w[3] = f3 * S;
}

// --- main eval: strict dense field from tables + gathers, 4+4 channels per z
__global__ void __launch_bounds__(256, 5) eval_kernel(const float* __restrict__ mask,
                                                      float* __restrict__ out) {
    int x = blockIdx.x * 256 + threadIdx.x;
    int y = blockIdx.y;
    int c0 = blockIdx.z * 4;                  // this block's 4 channels

    // ---- dense displacement, strict fp32 (bit-identical to reference) ------
    float4 wy = g_wy4[y];
    int mp = g_myp[y];
    const float* Rx = g_R + x;
    float d0 = 0.0f, d1 = 0.0f;
    {
        int j;
        j = mp & 3;
        d0 = __fadd_rn(d0, __fmul_rn(wy.x, __ldg(Rx + j*1024)));
        d1 = __fadd_rn(d1, __fmul_rn(wy.x, __ldg(Rx + (3+j)*1024)));
        j = (mp >> 2) & 3;
        d0 = __fadd_rn(d0, __fmul_rn(wy.y, __ldg(Rx + j*1024)));
        d1 = __fadd_rn(d1, __fmul_rn(wy.y, __ldg(Rx + (3+j)*1024)));
        j = (mp >> 4) & 3;
        d0 = __fadd_rn(d0, __fmul_rn(wy.z, __ldg(Rx + j*1024)));
        d1 = __fadd_rn(d1, __fmul_rn(wy.z, __ldg(Rx + (3+j)*1024)));
        j = (mp >> 6) & 3;
        d0 = __fadd_rn(d0, __fmul_rn(wy.w, __ldg(Rx + j*1024)));
        d1 = __fadd_rn(d1, __fmul_rn(wy.w, __ldg(Rx + (3+j)*1024)));
    }
    float sy = __fadd_rn((float)y, d0);
    float sx = __fadd_rn((float)x, d1);
    bool valid = (sy >= 0.0f) && (sy <= 1023.0f) && (sx >= 0.0f) && (sx <= 1023.0f);
    int oidx = y*Ww + x;

    if (valid) {
        float fs = floorf(sy); int iy = (int)fs; float fy = sy - fs;
        float gs = floorf(sx); int ix = (int)gs; float fx = sx - gs;
        float Wy[4], Wx[4];
        cubw_fast(fy, Wy); cubw_fast(fx, Wx);
        int ry[4], rx[4];
        #pragma unroll
        for (int a = 0; a < 4; a++) ry[a] = refl1024(iy + a - 1) * Ww;
        #pragma unroll
        for (int b = 0; b < 4; b++) rx[b] = refl1024(ix + b - 1);

        #pragma unroll
        for (int cc = 0; cc < 4; cc++) {
            const float* p = g_coef + (c0 + cc) * HW;
            float s = 0.0f;
            #pragma unroll
            for (int a = 0; a < 4; a++) {
                const float* pr = p + ry[a];
                float row;
                row = Wx[0] * __ldg(pr + rx[0]);
                row = fmaf(Wx[1], __ldg(pr + rx[1]), row);
                row = fmaf(Wx[2], __ldg(pr + rx[2]), row);
                row = fmaf(Wx[3], __ldg(pr + rx[3]), row);
                s = fmaf(Wy[a], row, s);
            }
            out[(c0 + cc)*HW + oidx] = s;
        }
        int ny = (int)rintf(sy); ny = ny < 0 ? 0 : (ny > 1023 ? 1023 : ny);  // half-even
        int nx = (int)rintf(sx); nx = nx < 0 ? 0 : (nx > 1023 ? 1023 : nx);
        int midx = ny*Ww + nx;
        #pragma unroll
        for (int cc = 0; cc < 4; cc++)
            out[(Cc + c0 + cc)*HW + oidx] = __ldg(mask + (c0 + cc)*HW + midx);
    } else {
        #pragma unroll
        for (int cc = 0; cc < 4; cc++) {
            out[(c0 + cc)*HW + oidx] = 0.0f;
            out[(Cc + c0 + cc)*HW + oidx] = 0.0f;
        }
    }
}

extern "C" void kernel_launch(void* const* d_in, const int* in_sizes, int n_in,
                              void* d_out, int out_size) {
    const float* image = (const float*)d_in[0];
    const float* mask  = (const float*)d_in[1];
    const float* disp  = (const float*)d_in[2];
    float* out = (float*)d_out;

    static int smem_set = 0;
    if (!smem_set) {
        cudaFuncSetAttribute(prefilt_kernel,
                             cudaFuncAttributeMaxDynamicSharedMemorySize, PSMEM);
        smem_set = 1;
    }

    setup_kernel<<<1, 32>>>(disp);
    table_kernel<<<4, 256>>>();
    prefilt_kernel<<<dim3(8, 8, 16), 256, PSMEM>>>(image);
    eval_kernel<<<dim3(4, 1024, 4), 256>>>(mask, out);
}